// round 8
// baseline (speedup 1.0000x reference)
#include <cuda_runtime.h>
#include <cstdint>

// ==================== constants ====================
#define BSZ    8192
#define HDIM   1024
#define KTOT   2048           // I + H
#define BTILE  128            // batch rows per CTA
#define HT     32             // h-cols per CTA (per gate)
#define KC     32             // K per chunk
#define NCHUNK (KTOT / KC)    // 64
#define NSTAGE 3
#define A_FLOATS ((size_t)BSZ * KTOT)        // 16M
#define W_FLOATS ((size_t)4 * HDIM * KTOT)   // 8M
#define CMOFF  ((size_t)BSZ * HDIM)

// per-chunk smem: A 16KB (fragment order) + W 16KB (4 gates x 4KB)
#define STAGE_F   8192                        // floats per stage (32KB)
#define SMEM_BYTES (NSTAGE * STAGE_F * 4)     // 98304

__device__ float g_scr[A_FLOATS + W_FLOATS];  // tf32-rounded, fragment-permuted

// ==================== helpers ====================
__device__ __forceinline__ uint32_t smem_u32(const void* p) {
    uint32_t a;
    asm("{ .reg .u64 t; cvta.to.shared.u64 t, %1; cvt.u32.u64 %0, t; }" : "=r"(a) : "l"(p));
    return a;
}
__device__ __forceinline__ void cp_async16(uint32_t dst, const void* src) {
    asm volatile("cp.async.cg.shared.global [%0], [%1], 16;" :: "r"(dst), "l"(src) : "memory");
}
__device__ __forceinline__ float rnd_tf32(float f) {
    uint32_t u;
    asm("cvt.rna.tf32.f32 %0, %1;" : "=r"(u) : "f"(f));
    return __uint_as_float(u);
}
__device__ __forceinline__ void mma_tf32(float* d, const uint32_t* a, uint32_t b0, uint32_t b1) {
    asm volatile(
        "mma.sync.aligned.m16n8k8.row.col.f32.tf32.tf32.f32 "
        "{%0,%1,%2,%3}, {%4,%5,%6,%7}, {%8,%9}, {%0,%1,%2,%3};"
        : "+f"(d[0]), "+f"(d[1]), "+f"(d[2]), "+f"(d[3])
        : "r"(a[0]), "r"(a[1]), "r"(a[2]), "r"(a[3]), "r"(b0), "r"(b1));
}
__device__ __forceinline__ float sigm(float z) {
    return __fdividef(1.0f, 1.0f + __expf(-z));
}
__device__ __forceinline__ float tanh_(float z) {
    float e = __expf(-2.0f * z);
    return (1.0f - e) * __fdividef(1.0f, 1.0f + e);
}

// ==================== prep: round to tf32 + permute to fragment order ====================
// A region (16M floats): [b_blk 64][kc 64][mt 8][k8 4][lane 32] x float4
//   float4 = (S[r0][c0], S[r0+8][c0], S[r0][c0+4], S[r0+8][c0+4])
//   r0 = b_blk*128 + mt*16 + gid, c0 = kc*32 + k8*8 + tg   (gid=lane>>2, tg=lane&3)
// W region (8M floats): [g 4][h_blk 32][kc 64][ntp 2][k8 4][lane 32] x float4
//   float4 = (W[n0][k], W[n0][k+4], W[n0+8][k], W[n0+8][k+4])
//   n0 = h_blk*32 + ntp*16 + gid, k = kc*32 + k8*8 + tg
__global__ void __launch_bounds__(256) prep_kernel(
    const float* __restrict__ x, const float* __restrict__ h,
    const float* __restrict__ Wxi, const float* __restrict__ Whi,
    const float* __restrict__ Wxf, const float* __restrict__ Whf,
    const float* __restrict__ Wxc, const float* __restrict__ Whc,
    const float* __restrict__ Wxo, const float* __restrict__ Who)
{
    const long t = (long)blockIdx.x * blockDim.x + threadIdx.x;
    const long A_V = (long)(A_FLOATS / 4);       // 4M float4 slots
    const long W_V = (long)(W_FLOATS / 4);       // 2M float4 slots
    if (t < A_V) {
        const long o = t;
        const int lane = (int)(o & 31);
        const int k8   = (int)((o >> 5) & 3);
        const int mt   = (int)((o >> 7) & 7);
        const int kc   = (int)((o >> 10) & 63);
        const int bb   = (int)(o >> 16);
        const int gid = lane >> 2, tg = lane & 3;
        const int r0 = bb * 128 + mt * 16 + gid;
        const int c0 = kc * 32 + k8 * 8 + tg;
        const float* S = (c0 < 1024) ? x : h;
        const int cc = (c0 < 1024) ? c0 : c0 - 1024;
        float4 v;
        v.x = rnd_tf32(S[(size_t)r0 * 1024 + cc]);
        v.y = rnd_tf32(S[(size_t)(r0 + 8) * 1024 + cc]);
        v.z = rnd_tf32(S[(size_t)r0 * 1024 + cc + 4]);
        v.w = rnd_tf32(S[(size_t)(r0 + 8) * 1024 + cc + 4]);
        *(float4*)(g_scr + (size_t)o * 4) = v;
    } else if (t < A_V + W_V) {
        const long o = t - A_V;
        const int lane = (int)(o & 31);
        const int k8   = (int)((o >> 5) & 3);
        const int ntp  = (int)((o >> 7) & 1);
        const int kc   = (int)((o >> 8) & 63);
        const int hb   = (int)((o >> 14) & 31);
        const int g    = (int)(o >> 19);
        const int gid = lane >> 2, tg = lane & 3;
        const int n0 = hb * 32 + ntp * 16 + gid;
        const int k  = kc * 32 + k8 * 8 + tg;
        const float* wx = (g == 0) ? Wxi : (g == 1) ? Wxf : (g == 2) ? Wxc : Wxo;
        const float* wh = (g == 0) ? Whi : (g == 1) ? Whf : (g == 2) ? Whc : Who;
        const float* S = (k < 1024) ? wx : wh;
        const int kk = (k < 1024) ? k : k - 1024;
        float4 v;
        v.x = rnd_tf32(S[(size_t)n0 * 1024 + kk]);
        v.y = rnd_tf32(S[(size_t)n0 * 1024 + kk + 4]);
        v.z = rnd_tf32(S[(size_t)(n0 + 8) * 1024 + kk]);
        v.w = rnd_tf32(S[(size_t)(n0 + 8) * 1024 + kk + 4]);
        *(float4*)(g_scr + A_FLOATS + (size_t)o * 4) = v;
    }
}

// ==================== main fused LSTM ====================
__global__ void __launch_bounds__(256, 2) lstm_fused(
    const float* __restrict__ c_prev,
    const float* __restrict__ bxi, const float* __restrict__ bhi,
    const float* __restrict__ bxf, const float* __restrict__ bhf,
    const float* __restrict__ bxc, const float* __restrict__ bhc,
    const float* __restrict__ bxo, const float* __restrict__ bho,
    float* __restrict__ out)
{
    extern __shared__ float smf[];
    const uint32_t sb = smem_u32(smf);

    const int tid   = threadIdx.x;
    const int wid   = tid >> 5;
    const int lane  = tid & 31;
    const int gid   = lane >> 2;
    const int tg    = lane & 3;
    const int warp_m = wid >> 2;   // 0..1
    const int warp_n = wid & 3;    // 0..3 == gate

    const int hb = blockIdx.x;           // 0..31
    const int bb = blockIdx.y;           // 0..63
    const int h0 = hb * HT;
    const int b0 = bb * BTILE;

    const float* Achunk0 = g_scr + (size_t)bb * 64 * 4096;   // + kc*4096
    const float* Wchunk0 = g_scr + A_FLOATS;

    auto issue_chunk = [&](int kc) {
        const int s = kc % NSTAGE;
        const uint32_t stb = sb + (uint32_t)(s * STAGE_F) * 4u;
        const float* asrc = Achunk0 + (size_t)kc * 4096;
        #pragma unroll
        for (int t = 0; t < 4; t++) {        // A: 1024 x 16B
            const int idx = t * 256 + tid;
            cp_async16(stb + (uint32_t)idx * 16u, asrc + (size_t)idx * 4);
        }
        #pragma unroll
        for (int t = 0; t < 4; t++) {        // W: 1024 x 16B (4 gates x 4KB)
            const int idx = t * 256 + tid;
            const int g  = idx >> 8;
            const int wi = idx & 255;
            const float* wsrc = Wchunk0 + (((size_t)g * 32 + hb) * 64 + kc) * 1024
                              + (size_t)wi * 4;
            cp_async16(stb + 16384u + (uint32_t)idx * 16u, wsrc);
        }
        asm volatile("cp.async.commit_group;" ::: "memory");
    };

    float acc[4][4][4];
    #pragma unroll
    for (int a = 0; a < 4; a++)
        #pragma unroll
        for (int b = 0; b < 4; b++)
            #pragma unroll
            for (int c = 0; c < 4; c++) acc[a][b][c] = 0.0f;

    issue_chunk(0);
    issue_chunk(1);

    for (int i = 0; i < NCHUNK; i++) {
        if (i < NCHUNK - 1) asm volatile("cp.async.wait_group 1;" ::: "memory");
        else                asm volatile("cp.async.wait_group 0;" ::: "memory");
        __syncthreads();
        // Overwrites the stage chunk i-1 used; every warp passed this iteration's
        // barrier only after finishing compute(i-1), so the stage is free.
        if (i + 2 < NCHUNK) issue_chunk(i + 2);

        const int s = i % NSTAGE;
        const float4* Af = (const float4*)(smf + s * STAGE_F);
        const float4* Bf = (const float4*)(smf + s * STAGE_F + 4096 + warp_n * 1024);

        #pragma unroll
        for (int k8 = 0; k8 < 4; k8++) {
            uint32_t af[4][4];
            float4 bv[2];
            #pragma unroll
            for (int mt = 0; mt < 4; mt++) {
                float4 v = Af[((warp_m * 4 + mt) * 4 + k8) * 32 + lane];
                af[mt][0] = __float_as_uint(v.x);
                af[mt][1] = __float_as_uint(v.y);
                af[mt][2] = __float_as_uint(v.z);
                af[mt][3] = __float_as_uint(v.w);
            }
            #pragma unroll
            for (int ntp = 0; ntp < 2; ntp++)
                bv[ntp] = Bf[(ntp * 4 + k8) * 32 + lane];
            #pragma unroll
            for (int mt = 0; mt < 4; mt++) {
                #pragma unroll
                for (int ntp = 0; ntp < 2; ntp++) {
                    mma_tf32(acc[mt][2 * ntp],
                             af[mt], __float_as_uint(bv[ntp].x), __float_as_uint(bv[ntp].y));
                    mma_tf32(acc[mt][2 * ntp + 1],
                             af[mt], __float_as_uint(bv[ntp].z), __float_as_uint(bv[ntp].w));
                }
            }
        }
    }

    // ---------- epilogue: gate exchange through smem ----------
    __syncthreads();
    {
        float* ep = smf + warp_n * 4096;   // plane [128][32]
        #pragma unroll
        for (int mt = 0; mt < 4; mt++) {
            #pragma unroll
            for (int nt = 0; nt < 4; nt++) {
                const int r = warp_m * 64 + mt * 16 + gid;
                const int c = nt * 8 + 2 * tg;
                *(float2*)(ep + r * 32 + c)       = make_float2(acc[mt][nt][0], acc[mt][nt][1]);
                *(float2*)(ep + (r + 8) * 32 + c) = make_float2(acc[mt][nt][2], acc[mt][nt][3]);
            }
        }
    }
    __syncthreads();

    {
        const int col = tid & 31;
        const int grp = tid >> 5;
        const int h   = h0 + col;
        const float bi  = bxi[h] + bhi[h];
        const float bfv = bxf[h] + bhf[h];
        const float bc  = bxc[h] + bhc[h];
        const float bo  = bxo[h] + bho[h];
        const float* ep = smf;

        #pragma unroll
        for (int j = 0; j < 16; j++) {
            const int r  = grp * 16 + j;
            const int gb = b0 + r;
            const int o_ = r * 32 + col;
            const float zi = ep[o_]         + bi;
            const float zf = ep[4096 + o_]  + bfv;
            const float zc = ep[8192 + o_]  + bc;
            const float zo = ep[12288 + o_] + bo;
            const float iv = sigm(zi), fv = sigm(zf);
            const float gv = tanh_(zc), ov = sigm(zo);
            const float cp = c_prev[(size_t)gb * 1024 + h];
            const float cn = fv * cp + iv * gv;
            out[(size_t)gb * 1024 + h]         = ov * tanh_(cn);
            out[CMOFF + (size_t)gb * 1024 + h] = cn;
        }
    }
}

// ==================== launch ====================
extern "C" void kernel_launch(void* const* d_in, const int* in_sizes, int n_in,
                              void* d_out, int out_size) {
    const float* x      = (const float*)d_in[0];
    const float* h_prev = (const float*)d_in[1];
    const float* c_prev = (const float*)d_in[2];
    const float* Wxi = (const float*)d_in[3];
    const float* Whi = (const float*)d_in[4];
    const float* Wxf = (const float*)d_in[5];
    const float* Whf = (const float*)d_in[6];
    const float* Wxc = (const float*)d_in[7];
    const float* Whc = (const float*)d_in[8];
    const float* Wxo = (const float*)d_in[9];
    const float* Who = (const float*)d_in[10];
    const float* bxi = (const float*)d_in[11];
    const float* bhi = (const float*)d_in[12];
    const float* bxf = (const float*)d_in[13];
    const float* bhf = (const float*)d_in[14];
    const float* bxc = (const float*)d_in[15];
    const float* bhc = (const float*)d_in[16];
    const float* bxo = (const float*)d_in[17];
    const float* bho = (const float*)d_in[18];
    float* out = (float*)d_out;

    cudaFuncSetAttribute(lstm_fused, cudaFuncAttributeMaxDynamicSharedMemorySize, SMEM_BYTES);

    // prep: 4M float4 (A) + 2M float4 (W) = 6M threads
    const long total = (long)(A_FLOATS / 4 + W_FLOATS / 4);
    prep_kernel<<<(unsigned)((total + 255) / 256), 256>>>(x, h_prev,
        Wxi, Whi, Wxf, Whf, Wxc, Whc, Wxo, Who);

    dim3 grid(HDIM / HT, BSZ / BTILE);   // (32, 64)
    lstm_fused<<<grid, 256, SMEM_BYTES>>>(
        c_prev,
        bxi, bhi, bxf, bhf, bxc, bhc, bxo, bho,
        out);
}

// round 9
// speedup vs baseline: 1.7571x; 1.7571x over previous
#include <cuda_runtime.h>
#include <cuda_fp16.h>
#include <cstdint>

// ==================== constants ====================
#define BSZ    8192
#define HDIM   1024
#define KTOT   2048           // I + H
#define BTILE  128            // batch rows per CTA
#define HT     32             // h-cols per CTA (per gate)
#define KC     32             // K per chunk (2 x k16 steps)
#define NCHUNK (KTOT / KC)    // 64
#define NSTAGE 3
#define CMOFF  ((size_t)BSZ * HDIM)

// fragment-packed fp16 scratch, as uint4 (16B) slots
#define A_SLOTS ((size_t)64 * 64 * 8 * 2 * 32)   // [bb][kc][mt][ks][lane] = 2M
#define W_SLOTS ((size_t)4 * 32 * 64 * 2 * 2 * 32) // [g][hb][kc][ntp][ks][lane] = 1M
__device__ uint4 g_scr[A_SLOTS + W_SLOTS];       // 48MB

// smem: stage = A 8KB + W 8KB = 16KB; 3 stages = 48KB; epilogue needs 64KB
#define STAGE_B   16384u
#define SMEM_BYTES 65536

// ==================== helpers ====================
__device__ __forceinline__ uint32_t smem_u32(const void* p) {
    uint32_t a;
    asm("{ .reg .u64 t; cvta.to.shared.u64 t, %1; cvt.u32.u64 %0, t; }" : "=r"(a) : "l"(p));
    return a;
}
__device__ __forceinline__ void cp_async16(uint32_t dst, const void* src) {
    asm volatile("cp.async.cg.shared.global [%0], [%1], 16;" :: "r"(dst), "l"(src) : "memory");
}
__device__ __forceinline__ void mma_f16(float* d, const uint4& a, uint32_t b0, uint32_t b1) {
    asm volatile(
        "mma.sync.aligned.m16n8k16.row.col.f32.f16.f16.f32 "
        "{%0,%1,%2,%3}, {%4,%5,%6,%7}, {%8,%9}, {%0,%1,%2,%3};"
        : "+f"(d[0]), "+f"(d[1]), "+f"(d[2]), "+f"(d[3])
        : "r"(a.x), "r"(a.y), "r"(a.z), "r"(a.w), "r"(b0), "r"(b1));
}
__device__ __forceinline__ uint32_t h2(float lo, float hi) {
    __half2 v = __floats2half2_rn(lo, hi);
    return *reinterpret_cast<uint32_t*>(&v);
}
__device__ __forceinline__ float sigm(float z) {
    return __fdividef(1.0f, 1.0f + __expf(-z));
}
__device__ __forceinline__ float tanh_(float z) {
    float e = __expf(-2.0f * z);
    return (1.0f - e) * __fdividef(1.0f, 1.0f + e);
}

// ==================== prep: fp16 convert + fragment pack ====================
// A slot (bb,kc,mt,ks,lane): r0 = bb*128+mt*16+gid, k0 = kc*32+ks*16, c = k0+2*tg
//   uint4 = (a0,a1,a2,a3) = h2(S[r0][c],S[r0][c+1]), h2(S[r0+8][c],..), h2(S[r0][c+8],..), h2(S[r0+8][c+8],..)
// W slot (g,hb,kc,ntp,ks,lane): n_a = hb*32+ntp*16+gid, n_b = n_a+8, k as above
//   uint4 = (b0(nt_a), b1(nt_a), b0(nt_b), b1(nt_b));  b0 = h2(W[n][c],W[n][c+1]), b1 = h2(W[n][c+8],W[n][c+9])
__global__ void __launch_bounds__(256) prep_kernel(
    const float* __restrict__ x, const float* __restrict__ h,
    const float* __restrict__ Wxi, const float* __restrict__ Whi,
    const float* __restrict__ Wxf, const float* __restrict__ Whf,
    const float* __restrict__ Wxc, const float* __restrict__ Whc,
    const float* __restrict__ Wxo, const float* __restrict__ Who)
{
    const long t = (long)blockIdx.x * blockDim.x + threadIdx.x;
    if (t < (long)A_SLOTS) {
        const long o = t;
        const int lane = (int)(o & 31);
        const int ks   = (int)((o >> 5) & 1);
        const int mt   = (int)((o >> 6) & 7);
        const int kc   = (int)((o >> 9) & 63);
        const int bb   = (int)(o >> 15);
        const int gid = lane >> 2, tg = lane & 3;
        const int r0 = bb * 128 + mt * 16 + gid;
        const int c  = kc * 32 + ks * 16 + 2 * tg;   // global k col
        const float* S = (c < 1024) ? x : h;
        const int cc = (c < 1024) ? c : c - 1024;
        const float* p0 = S + (size_t)r0 * 1024 + cc;
        const float* p1 = S + (size_t)(r0 + 8) * 1024 + cc;
        uint4 v;
        v.x = h2(p0[0], p0[1]);
        v.y = h2(p1[0], p1[1]);
        v.z = h2(p0[8], p0[9]);
        v.w = h2(p1[8], p1[9]);
        g_scr[o] = v;
    } else if (t < (long)(A_SLOTS + W_SLOTS)) {
        const long o = t - (long)A_SLOTS;
        const int lane = (int)(o & 31);
        const int ks   = (int)((o >> 5) & 1);
        const int ntp  = (int)((o >> 6) & 1);
        const int kc   = (int)((o >> 7) & 63);
        const int hb   = (int)((o >> 13) & 31);
        const int g    = (int)(o >> 18);
        const int gid = lane >> 2, tg = lane & 3;
        const int n_a = hb * 32 + ntp * 16 + gid;
        const int c   = kc * 32 + ks * 16 + 2 * tg;
        const float* wx = (g == 0) ? Wxi : (g == 1) ? Wxf : (g == 2) ? Wxc : Wxo;
        const float* wh = (g == 0) ? Whi : (g == 1) ? Whf : (g == 2) ? Whc : Who;
        const float* S = (c < 1024) ? wx : wh;
        const int cc = (c < 1024) ? c : c - 1024;
        const float* pa = S + (size_t)n_a * 1024 + cc;
        const float* pb = S + (size_t)(n_a + 8) * 1024 + cc;
        uint4 v;
        v.x = h2(pa[0], pa[1]);
        v.y = h2(pa[8], pa[9]);
        v.z = h2(pb[0], pb[1]);
        v.w = h2(pb[8], pb[9]);
        g_scr[A_SLOTS + (size_t)o] = v;
    }
}

// ==================== main fused LSTM ====================
__global__ void __launch_bounds__(256, 2) lstm_fused(
    const float* __restrict__ c_prev,
    const float* __restrict__ bxi, const float* __restrict__ bhi,
    const float* __restrict__ bxf, const float* __restrict__ bhf,
    const float* __restrict__ bxc, const float* __restrict__ bhc,
    const float* __restrict__ bxo, const float* __restrict__ bho,
    float* __restrict__ out)
{
    extern __shared__ float smf[];
    const uint32_t sb = smem_u32(smf);

    const int tid   = threadIdx.x;
    const int wid   = tid >> 5;
    const int lane  = tid & 31;
    const int gid   = lane >> 2;
    const int tg    = lane & 3;
    const int warp_m = wid >> 2;   // 0..1
    const int warp_n = wid & 3;    // 0..3 == gate

    const int hb = blockIdx.x;           // 0..31
    const int bb = blockIdx.y;           // 0..63
    const int h0 = hb * HT;
    const int b0 = bb * BTILE;

    const uint4* Abase = g_scr + (size_t)bb * 64 * 512;     // + kc*512
    const uint4* Wbase = g_scr + A_SLOTS;                    // [g][hb][kc] * 128

    auto issue_chunk = [&](int kc) {
        const int s = kc % NSTAGE;
        const uint32_t stb = sb + (uint32_t)s * STAGE_B;
        const uint4* asrc = Abase + (size_t)kc * 512;
        #pragma unroll
        for (int t = 0; t < 2; t++) {        // A: 512 x 16B
            const int idx = t * 256 + tid;
            cp_async16(stb + (uint32_t)idx * 16u, asrc + idx);
        }
        #pragma unroll
        for (int t = 0; t < 2; t++) {        // W: 512 x 16B (4 gates x 2KB)
            const int idx = t * 256 + tid;
            const int g  = idx >> 7;
            const int wi = idx & 127;
            const uint4* wsrc = Wbase + ((size_t)g * 32 + hb) * 64 * 128
                              + (size_t)kc * 128 + wi;
            cp_async16(stb + 8192u + (uint32_t)idx * 16u, wsrc);
        }
        asm volatile("cp.async.commit_group;" ::: "memory");
    };

    float acc[4][4][4];
    #pragma unroll
    for (int a = 0; a < 4; a++)
        #pragma unroll
        for (int b = 0; b < 4; b++)
            #pragma unroll
            for (int c = 0; c < 4; c++) acc[a][b][c] = 0.0f;

    issue_chunk(0);
    issue_chunk(1);

    for (int i = 0; i < NCHUNK; i++) {
        if (i < NCHUNK - 1) asm volatile("cp.async.wait_group 1;" ::: "memory");
        else                asm volatile("cp.async.wait_group 0;" ::: "memory");
        __syncthreads();
        if (i + 2 < NCHUNK) issue_chunk(i + 2);

        const int s = i % NSTAGE;
        const uint4* Af = (const uint4*)((const char*)smf + s * STAGE_B);
        const uint4* Bf = (const uint4*)((const char*)smf + s * STAGE_B + 8192 + warp_n * 2048);

        #pragma unroll
        for (int ks = 0; ks < 2; ks++) {
            uint4 av[4], bv[2];
            #pragma unroll
            for (int mt = 0; mt < 4; mt++)
                av[mt] = Af[((warp_m * 4 + mt) * 2 + ks) * 32 + lane];
            #pragma unroll
            for (int ntp = 0; ntp < 2; ntp++)
                bv[ntp] = Bf[(ntp * 2 + ks) * 32 + lane];
            #pragma unroll
            for (int mt = 0; mt < 4; mt++) {
                #pragma unroll
                for (int ntp = 0; ntp < 2; ntp++) {
                    mma_f16(acc[mt][2 * ntp],     av[mt], bv[ntp].x, bv[ntp].y);
                    mma_f16(acc[mt][2 * ntp + 1], av[mt], bv[ntp].z, bv[ntp].w);
                }
            }
        }
    }

    // ---------- epilogue: gate exchange through smem ----------
    __syncthreads();
    {
        float* ep = smf + warp_n * 4096;   // plane [128][32]
        #pragma unroll
        for (int mt = 0; mt < 4; mt++) {
            #pragma unroll
            for (int nt = 0; nt < 4; nt++) {
                const int r = warp_m * 64 + mt * 16 + gid;
                const int c = nt * 8 + 2 * tg;
                *(float2*)(ep + r * 32 + c)       = make_float2(acc[mt][nt][0], acc[mt][nt][1]);
                *(float2*)(ep + (r + 8) * 32 + c) = make_float2(acc[mt][nt][2], acc[mt][nt][3]);
            }
        }
    }
    __syncthreads();

    {
        const int col = tid & 31;
        const int grp = tid >> 5;
        const int h   = h0 + col;
        const float bi  = bxi[h] + bhi[h];
        const float bfv = bxf[h] + bhf[h];
        const float bc  = bxc[h] + bhc[h];
        const float bo  = bxo[h] + bho[h];
        const float* ep = smf;

        #pragma unroll
        for (int j = 0; j < 16; j++) {
            const int r  = grp * 16 + j;
            const int gb = b0 + r;
            const int o_ = r * 32 + col;
            const float zi = ep[o_]         + bi;
            const float zf = ep[4096 + o_]  + bfv;
            const float zc = ep[8192 + o_]  + bc;
            const float zo = ep[12288 + o_] + bo;
            const float iv = sigm(zi), fv = sigm(zf);
            const float gv = tanh_(zc), ov = sigm(zo);
            const float cp = c_prev[(size_t)gb * 1024 + h];
            const float cn = fv * cp + iv * gv;
            out[(size_t)gb * 1024 + h]         = ov * tanh_(cn);
            out[CMOFF + (size_t)gb * 1024 + h] = cn;
        }
    }
}

// ==================== launch ====================
extern "C" void kernel_launch(void* const* d_in, const int* in_sizes, int n_in,
                              void* d_out, int out_size) {
    const float* x      = (const float*)d_in[0];
    const float* h_prev = (const float*)d_in[1];
    const float* c_prev = (const float*)d_in[2];
    const float* Wxi = (const float*)d_in[3];
    const float* Whi = (const float*)d_in[4];
    const float* Wxf = (const float*)d_in[5];
    const float* Whf = (const float*)d_in[6];
    const float* Wxc = (const float*)d_in[7];
    const float* Whc = (const float*)d_in[8];
    const float* Wxo = (const float*)d_in[9];
    const float* Who = (const float*)d_in[10];
    const float* bxi = (const float*)d_in[11];
    const float* bhi = (const float*)d_in[12];
    const float* bxf = (const float*)d_in[13];
    const float* bhf = (const float*)d_in[14];
    const float* bxc = (const float*)d_in[15];
    const float* bhc = (const float*)d_in[16];
    const float* bxo = (const float*)d_in[17];
    const float* bho = (const float*)d_in[18];
    float* out = (float*)d_out;

    cudaFuncSetAttribute(lstm_fused, cudaFuncAttributeMaxDynamicSharedMemorySize, SMEM_BYTES);

    const long total = (long)(A_SLOTS + W_SLOTS);   // 3M threads
    prep_kernel<<<(unsigned)((total + 255) / 256), 256>>>(x, h_prev,
        Wxi, Whi, Wxf, Whf, Wxc, Whc, Wxo, Who);

    dim3 grid(HDIM / HT, BSZ / BTILE);   // (32, 64)
    lstm_fused<<<grid, 256, SMEM_BYTES>>>(
        c_prev,
        bxi, bhi, bxf, bhf, bxc, bhc, bxo, bho,
        out);
}

// round 10
// speedup vs baseline: 1.8276x; 1.0401x over previous
#include <cuda_runtime.h>
#include <cuda_fp16.h>
#include <cstdint>

// ==================== constants ====================
#define BSZ    8192
#define HDIM   1024
#define KTOT   2048           // I + H
#define BTILE  128            // batch rows per CTA
#define HT     32             // h-cols per CTA (per gate)
#define KC     64             // K per chunk (4 x k16 steps)
#define NCHUNK (KTOT / KC)    // 32
#define NSTAGE 3
#define CMOFF  ((size_t)BSZ * HDIM)

// fragment-packed fp16 scratch, uint4 (16B) slots
// A: [bb 64][kc 32][mt 8][ks 4][lane 32]  = 2M slots
// W: [g 4][hb 32][kc 32][ntp 2][ks 4][lane 32] = 1M slots
#define A_SLOTS ((size_t)64 * 32 * 8 * 4 * 32)
#define W_SLOTS ((size_t)4 * 32 * 32 * 2 * 4 * 32)
__device__ uint4 g_scr[A_SLOTS + W_SLOTS];       // 48MB

// smem: stage = A 16KB + W 16KB = 32KB; 3 stages = 96KB (epilogue reuses 64KB)
#define STAGE_B   32768u
#define SMEM_BYTES (3 * 32768)

// ==================== helpers ====================
__device__ __forceinline__ uint32_t smem_u32(const void* p) {
    uint32_t a;
    asm("{ .reg .u64 t; cvta.to.shared.u64 t, %1; cvt.u32.u64 %0, t; }" : "=r"(a) : "l"(p));
    return a;
}
__device__ __forceinline__ void cp_async16(uint32_t dst, const void* src) {
    asm volatile("cp.async.cg.shared.global [%0], [%1], 16;" :: "r"(dst), "l"(src) : "memory");
}
__device__ __forceinline__ void mma_f16(float* d, const uint4& a, uint32_t b0, uint32_t b1) {
    asm volatile(
        "mma.sync.aligned.m16n8k16.row.col.f32.f16.f16.f32 "
        "{%0,%1,%2,%3}, {%4,%5,%6,%7}, {%8,%9}, {%0,%1,%2,%3};"
        : "+f"(d[0]), "+f"(d[1]), "+f"(d[2]), "+f"(d[3])
        : "r"(a.x), "r"(a.y), "r"(a.z), "r"(a.w), "r"(b0), "r"(b1));
}
__device__ __forceinline__ uint32_t h2(float lo, float hi) {
    __half2 v = __floats2half2_rn(lo, hi);
    return *reinterpret_cast<uint32_t*>(&v);
}
__device__ __forceinline__ float sigm(float z) {
    return __fdividef(1.0f, 1.0f + __expf(-z));
}
__device__ __forceinline__ float tanh_(float z) {
    float e = __expf(-2.0f * z);
    return (1.0f - e) * __fdividef(1.0f, 1.0f + e);
}

// ==================== prep: fp16 convert + fragment pack ====================
// A slot (bb,kc,mt,ks,lane): r0 = bb*128+mt*16+gid, c = kc*64+ks*16+2*tg
//   uint4 = h2(S[r0][c..c+1]), h2(S[r0+8][c..]), h2(S[r0][c+8..]), h2(S[r0+8][c+8..])
// W slot (g,hb,kc,ntp,ks,lane): n_a = hb*32+ntp*16+gid; same c
//   uint4 = h2(W[n_a][c..]), h2(W[n_a][c+8..]), h2(W[n_a+8][c..]), h2(W[n_a+8][c+8..])
__global__ void __launch_bounds__(256) prep_kernel(
    const float* __restrict__ x, const float* __restrict__ h,
    const float* __restrict__ Wxi, const float* __restrict__ Whi,
    const float* __restrict__ Wxf, const float* __restrict__ Whf,
    const float* __restrict__ Wxc, const float* __restrict__ Whc,
    const float* __restrict__ Wxo, const float* __restrict__ Who)
{
    const long t = (long)blockIdx.x * blockDim.x + threadIdx.x;
    if (t < (long)A_SLOTS) {
        const long o = t;
        const int lane = (int)(o & 31);
        const int ks   = (int)((o >> 5) & 3);
        const int mt   = (int)((o >> 7) & 7);
        const int kc   = (int)((o >> 10) & 31);
        const int bb   = (int)(o >> 15);
        const int gid = lane >> 2, tg = lane & 3;
        const int r0 = bb * 128 + mt * 16 + gid;
        const int c  = kc * 64 + ks * 16 + 2 * tg;
        const float* S = (c < 1024) ? x : h;
        const int cc = (c < 1024) ? c : c - 1024;
        const float* p0 = S + (size_t)r0 * 1024 + cc;
        const float* p1 = S + (size_t)(r0 + 8) * 1024 + cc;
        uint4 v;
        v.x = h2(p0[0], p0[1]);
        v.y = h2(p1[0], p1[1]);
        v.z = h2(p0[8], p0[9]);
        v.w = h2(p1[8], p1[9]);
        g_scr[o] = v;
    } else if (t < (long)(A_SLOTS + W_SLOTS)) {
        const long o = t - (long)A_SLOTS;
        const int lane = (int)(o & 31);
        const int ks   = (int)((o >> 5) & 3);
        const int ntp  = (int)((o >> 7) & 1);
        const int kc   = (int)((o >> 8) & 31);
        const int hb   = (int)((o >> 13) & 31);
        const int g    = (int)(o >> 18);
        const int gid = lane >> 2, tg = lane & 3;
        const int n_a = hb * 32 + ntp * 16 + gid;
        const int c   = kc * 64 + ks * 16 + 2 * tg;
        const float* wx = (g == 0) ? Wxi : (g == 1) ? Wxf : (g == 2) ? Wxc : Wxo;
        const float* wh = (g == 0) ? Whi : (g == 1) ? Whf : (g == 2) ? Whc : Who;
        const float* S = (c < 1024) ? wx : wh;
        const int cc = (c < 1024) ? c : c - 1024;
        const float* pa = S + (size_t)n_a * 1024 + cc;
        const float* pb = S + (size_t)(n_a + 8) * 1024 + cc;
        uint4 v;
        v.x = h2(pa[0], pa[1]);
        v.y = h2(pa[8], pa[9]);
        v.z = h2(pb[0], pb[1]);
        v.w = h2(pb[8], pb[9]);
        g_scr[A_SLOTS + (size_t)o] = v;
    }
}

// ==================== main fused LSTM ====================
__global__ void __launch_bounds__(256, 2) lstm_fused(
    const float* __restrict__ c_prev,
    const float* __restrict__ bxi, const float* __restrict__ bhi,
    const float* __restrict__ bxf, const float* __restrict__ bhf,
    const float* __restrict__ bxc, const float* __restrict__ bhc,
    const float* __restrict__ bxo, const float* __restrict__ bho,
    float* __restrict__ out)
{
    extern __shared__ float smf[];
    const uint32_t sb = smem_u32(smf);

    const int tid   = threadIdx.x;
    const int wid   = tid >> 5;
    const int lane  = tid & 31;
    const int gid   = lane >> 2;
    const int tg    = lane & 3;
    const int warp_m = wid >> 2;   // 0..1
    const int warp_n = wid & 3;    // 0..3 == gate

    const int hb = blockIdx.x;           // 0..31
    const int bb = blockIdx.y;           // 0..63
    const int h0 = hb * HT;
    const int b0 = bb * BTILE;

    const uint4* Abase = g_scr + (size_t)bb * 32 * 1024;    // + kc*1024
    const uint4* Wbase = g_scr + A_SLOTS;                    // [(g*32+hb)*32 + kc] * 256

    auto issue_chunk = [&](int kc) {
        const int s = kc % NSTAGE;
        const uint32_t stb = sb + (uint32_t)s * STAGE_B;
        const uint4* asrc = Abase + (size_t)kc * 1024;
        #pragma unroll
        for (int t = 0; t < 4; t++) {        // A: 1024 x 16B
            const int idx = t * 256 + tid;
            cp_async16(stb + (uint32_t)idx * 16u, asrc + idx);
        }
        #pragma unroll
        for (int t = 0; t < 4; t++) {        // W: 1024 x 16B (4 gates x 4KB)
            const int idx = t * 256 + tid;
            const int g  = idx >> 8;
            const int wi = idx & 255;
            const uint4* wsrc = Wbase + ((size_t)g * 32 + hb) * 32 * 256
                              + (size_t)kc * 256 + wi;
            cp_async16(stb + 16384u + (uint32_t)idx * 16u, wsrc);
        }
        asm volatile("cp.async.commit_group;" ::: "memory");
    };

    float acc[4][4][4];
    #pragma unroll
    for (int a = 0; a < 4; a++)
        #pragma unroll
        for (int b = 0; b < 4; b++)
            #pragma unroll
            for (int c = 0; c < 4; c++) acc[a][b][c] = 0.0f;

    issue_chunk(0);
    issue_chunk(1);

    for (int i = 0; i < NCHUNK; i++) {
        if (i < NCHUNK - 1) asm volatile("cp.async.wait_group 1;" ::: "memory");
        else                asm volatile("cp.async.wait_group 0;" ::: "memory");
        __syncthreads();
        if (i + 2 < NCHUNK) issue_chunk(i + 2);

        const int s = i % NSTAGE;
        const uint4* Af = (const uint4*)((const char*)smf + s * STAGE_B);
        const uint4* Bf = (const uint4*)((const char*)smf + s * STAGE_B + 16384 + warp_n * 4096);

        #pragma unroll
        for (int ks = 0; ks < 4; ks++) {
            uint4 av[4], bv[2];
            #pragma unroll
            for (int mt = 0; mt < 4; mt++)
                av[mt] = Af[((warp_m * 4 + mt) * 4 + ks) * 32 + lane];
            #pragma unroll
            for (int ntp = 0; ntp < 2; ntp++)
                bv[ntp] = Bf[(ntp * 4 + ks) * 32 + lane];
            #pragma unroll
            for (int mt = 0; mt < 4; mt++) {
                #pragma unroll
                for (int ntp = 0; ntp < 2; ntp++) {
                    mma_f16(acc[mt][2 * ntp],     av[mt], bv[ntp].x, bv[ntp].y);
                    mma_f16(acc[mt][2 * ntp + 1], av[mt], bv[ntp].z, bv[ntp].w);
                }
            }
        }
    }

    // ---------- epilogue: gate exchange through smem ----------
    __syncthreads();
    {
        float* ep = smf + warp_n * 4096;   // plane [128][32]
        #pragma unroll
        for (int mt = 0; mt < 4; mt++) {
            #pragma unroll
            for (int nt = 0; nt < 4; nt++) {
                const int r = warp_m * 64 + mt * 16 + gid;
                const int c = nt * 8 + 2 * tg;
                *(float2*)(ep + r * 32 + c)       = make_float2(acc[mt][nt][0], acc[mt][nt][1]);
                *(float2*)(ep + (r + 8) * 32 + c) = make_float2(acc[mt][nt][2], acc[mt][nt][3]);
            }
        }
    }
    __syncthreads();

    {
        const int col = tid & 31;
        const int grp = tid >> 5;
        const int h   = h0 + col;
        const float bi  = bxi[h] + bhi[h];
        const float bfv = bxf[h] + bhf[h];
        const float bc  = bxc[h] + bhc[h];
        const float bo  = bxo[h] + bho[h];
        const float* ep = smf;

        #pragma unroll
        for (int j = 0; j < 16; j++) {
            const int r  = grp * 16 + j;
            const int gb = b0 + r;
            const int o_ = r * 32 + col;
            const float zi = ep[o_]         + bi;
            const float zf = ep[4096 + o_]  + bfv;
            const float zc = ep[8192 + o_]  + bc;
            const float zo = ep[12288 + o_] + bo;
            const float iv = sigm(zi), fv = sigm(zf);
            const float gv = tanh_(zc), ov = sigm(zo);
            const float cp = c_prev[(size_t)gb * 1024 + h];
            const float cn = fv * cp + iv * gv;
            out[(size_t)gb * 1024 + h]         = ov * tanh_(cn);
            out[CMOFF + (size_t)gb * 1024 + h] = cn;
        }
    }
}

// ==================== launch ====================
extern "C" void kernel_launch(void* const* d_in, const int* in_sizes, int n_in,
                              void* d_out, int out_size) {
    const float* x      = (const float*)d_in[0];
    const float* h_prev = (const float*)d_in[1];
    const float* c_prev = (const float*)d_in[2];
    const float* Wxi = (const float*)d_in[3];
    const float* Whi = (const float*)d_in[4];
    const float* Wxf = (const float*)d_in[5];
    const float* Whf = (const float*)d_in[6];
    const float* Wxc = (const float*)d_in[7];
    const float* Whc = (const float*)d_in[8];
    const float* Wxo = (const float*)d_in[9];
    const float* Who = (const float*)d_in[10];
    const float* bxi = (const float*)d_in[11];
    const float* bhi = (const float*)d_in[12];
    const float* bxf = (const float*)d_in[13];
    const float* bhf = (const float*)d_in[14];
    const float* bxc = (const float*)d_in[15];
    const float* bhc = (const float*)d_in[16];
    const float* bxo = (const float*)d_in[17];
    const float* bho = (const float*)d_in[18];
    float* out = (float*)d_out;

    cudaFuncSetAttribute(lstm_fused, cudaFuncAttributeMaxDynamicSharedMemorySize, SMEM_BYTES);

    const long total = (long)(A_SLOTS + W_SLOTS);   // 3M threads
    prep_kernel<<<(unsigned)((total + 255) / 256), 256>>>(x, h_prev,
        Wxi, Whi, Wxf, Whf, Wxc, Whc, Wxo, Who);

    dim3 grid(HDIM / HT, BSZ / BTILE);   // (32, 64)
    lstm_fused<<<grid, 256, SMEM_BYTES>>>(
        c_prev,
        bxi, bhi, bxf, bhf, bxc, bhc, bxo, bho,
        out);
}